// round 7
// baseline (speedup 1.0000x reference)
#include <cuda_runtime.h>
#include <cuda_fp16.h>
#include <cstdint>

// ---------------- problem constants ----------------
#define N_ATT   512
#define N_DEC   1024
#define N_ENC2  1024
#define N_BATCH 32
#define N_SEQ   2048
#define N_ROWS  (N_BATCH * N_SEQ)   // 65536

// ---------------- device scratch (static globals; no runtime allocation) ----------------
__device__ __half g_encH[(size_t)N_ROWS * N_ENC2];  // fp16 copy of encoder (128 MB)
__device__ __half g_UTH[N_ATT * N_ENC2];            // U_w transposed fp16: [n][k]
__device__ float  g_WsUb[N_BATCH * N_ATT];          // dec@W_w + W_b + U_b
__device__ float  g_energy[N_ROWS];

// ---------------- helpers (plain sm_80+ PTX only) ----------------
__device__ __forceinline__ uint32_t smem_u32(const void* p) {
    uint32_t a;
    asm("{ .reg .u64 t; cvta.to.shared.u64 t, %1; cvt.u32.u64 %0, t; }"
        : "=r"(a) : "l"(p));
    return a;
}

__device__ __forceinline__ void cp16(uint32_t dst, const void* src) {
    asm volatile("cp.async.cg.shared.global [%0], [%1], 16;"
                 :: "r"(dst), "l"(src) : "memory");
}
__device__ __forceinline__ void cp_commit() {
    asm volatile("cp.async.commit_group;" ::: "memory");
}
template <int N>
__device__ __forceinline__ void cp_wait() {
    asm volatile("cp.async.wait_group %0;" :: "n"(N) : "memory");
}

__device__ __forceinline__ void ldsm4(uint32_t addr, uint32_t& r0, uint32_t& r1,
                                      uint32_t& r2, uint32_t& r3) {
    asm volatile("ldmatrix.sync.aligned.m8n8.x4.shared.b16 {%0,%1,%2,%3}, [%4];"
                 : "=r"(r0), "=r"(r1), "=r"(r2), "=r"(r3) : "r"(addr));
}

__device__ __forceinline__ void mma_f16(float* d, const uint32_t* a, const uint32_t* b) {
    asm volatile(
        "mma.sync.aligned.m16n8k16.row.col.f32.f16.f16.f32 "
        "{%0,%1,%2,%3}, {%4,%5,%6,%7}, {%8,%9}, {%0,%1,%2,%3};"
        : "+f"(d[0]), "+f"(d[1]), "+f"(d[2]), "+f"(d[3])
        : "r"(a[0]), "r"(a[1]), "r"(a[2]), "r"(a[3]), "r"(b[0]), "r"(b[1]));
}

// accurate tanh: 1 - 2/(exp(2x)+1) via ex2.approx + rcp.approx (~1e-6 err)
__device__ __forceinline__ float tanh_acc(float x) {
    float e, r;
    asm("ex2.approx.f32 %0, %1;" : "=f"(e) : "f"(x * 2.8853900817779268f));
    asm("rcp.approx.f32 %0, %1;" : "=f"(r) : "f"(e + 1.0f));
    return 1.0f - 2.0f * r;
}

// ---------------- kernel 1: transpose U_w into g_UTH[n][k] (fp16) ----------------
__global__ void ut_transpose_kernel(const float* __restrict__ Uw) {
    __shared__ float tile[32][33];
    int n0 = blockIdx.x * 32;
    int k0 = blockIdx.y * 32;
    int tx = threadIdx.x, ty = threadIdx.y;  // block (32, 8)
    #pragma unroll
    for (int j = 0; j < 32; j += 8)
        tile[ty + j][tx] = Uw[(size_t)(k0 + ty + j) * N_ATT + n0 + tx];
    __syncthreads();
    #pragma unroll
    for (int j = 0; j < 32; j += 8)
        g_UTH[(size_t)(n0 + ty + j) * N_ENC2 + k0 + tx] = __float2half_rn(tile[tx][ty + j]);
}

// ---------------- kernel 2: g_WsUb = dec @ W_w + W_b + U_b ----------------
__global__ void wsb_kernel(const float* __restrict__ dec, const float* __restrict__ Ww,
                           const float* __restrict__ Wb, const float* __restrict__ Ub) {
    int a = blockIdx.x * 256 + threadIdx.x;  // grid (2, 8)
    int b0 = blockIdx.y * 4;
    float acc[4] = {0.f, 0.f, 0.f, 0.f};
    #pragma unroll 2
    for (int k = 0; k < N_DEC; k++) {
        float w = Ww[(size_t)k * N_ATT + a];
        #pragma unroll
        for (int j = 0; j < 4; j++)
            acc[j] = fmaf(dec[(size_t)(b0 + j) * N_DEC + k], w, acc[j]);
    }
    float bias = Wb[a] + Ub[a];
    #pragma unroll
    for (int j = 0; j < 4; j++)
        g_WsUb[(size_t)(b0 + j) * N_ATT + a] = acc[j] + bias;
}

// ---------------- kernel 3: fused fp32-consuming GEMM + energy epilogue ----------------
// 512 CTAs x 256 thr, 1 CTA/SM (197KB smem). CTA = 128 rows x 512 cols as FOUR
// N=128 passes. Pass 0 loads A as fp32 (cp.async), converts in-SMEM to the swizzled
// fp16 A stage AND writes g_encH; passes 1-3 load A fp16 from g_encH. B fp16 always.
// K-tile 64, 3-stage pipeline, flat tile counter tc = pass*16 + kt.
// Warp layout: 2(M) x 4(N); warp tile 64x32; acc 64 f32/thread.
#define KT        64
#define NSTAGE    3
#define STG_A16   16384                 // 128 rows * 128B (fp16)
#define STG_B     16384                 // 128 n-rows * 128B (fp16)
#define STG_A32   32768                 // 128 rows * 256B (fp32), two 64-col subtiles
#define HDR       5120                  // e_sm(512) + wsb(2048) + vv(2048) + pad
#define OFF_A16   HDR
#define OFF_B     (HDR + NSTAGE * STG_A16)
#define OFF_A32   (HDR + NSTAGE * (STG_A16 + STG_B))
#define SMEM_MAIN (OFF_A32 + NSTAGE * STG_A32)   // 5120 + 98304 + 98304 = 201728 B
#define NTILES    64                    // 4 passes * 16 K-tiles

struct LoadCtx {
    uint32_t sb;
    const float* enc;
    int tid, row_base;
};

__device__ __forceinline__ void load_tile(const LoadCtx& L, int tc) {
    int pass = tc >> 4, kt = tc & 15;
    int s = tc % NSTAGE;
    if (pass == 0) {
        // A as fp32: 128 rows x 64 cols = 2048 x 16B chunks into A32[s]
        // layout: subtile sub (cols sub*32..+32), chunk (r, c): r*128 + ((c^(r&7))<<4)
        uint32_t a32 = L.sb + OFF_A32 + s * STG_A32;
        const float* Asrc = L.enc + (size_t)L.row_base * N_ENC2 + kt * KT;
        #pragma unroll
        for (int i = 0; i < 8; i++) {
            int q = L.tid + i * 256;
            int r = q >> 4, sub = (q >> 3) & 1, c = q & 7;
            cp16(a32 + sub * 16384 + r * 128 + (((uint32_t)(c ^ (r & 7))) << 4),
                 Asrc + (size_t)r * N_ENC2 + sub * 32 + c * 4);
        }
    } else {
        // A as fp16 from g_encH: 128 rows x 128B = 1024 x 16B chunks
        uint32_t a16 = L.sb + OFF_A16 + s * STG_A16;
        const __half* Asrc = g_encH + (size_t)L.row_base * N_ENC2 + kt * KT;
        #pragma unroll
        for (int i = 0; i < 4; i++) {
            int id = L.tid + i * 256;
            int r = id >> 3, c = id & 7;
            cp16(a16 + r * 128 + (((uint32_t)(c ^ (r & 7))) << 4),
                 Asrc + (size_t)r * N_ENC2 + c * 8);
        }
    }
    // B: 128 n-rows x 128B = 1024 x 16B chunks
    const __half* Bsrc = g_UTH + (size_t)(pass * 128) * N_ENC2 + kt * KT;
    uint32_t stB = L.sb + OFF_B + s * STG_B;
    #pragma unroll
    for (int i = 0; i < 4; i++) {
        int id = L.tid + i * 256;
        int n = id >> 3, c = id & 7;
        cp16(stB + n * 128 + (((uint32_t)(c ^ (n & 7))) << 4),
             Bsrc + (size_t)n * N_ENC2 + c * 8);
    }
    cp_commit();
}

__global__ void __launch_bounds__(256, 1)
attn_energy_kernel(const float* __restrict__ enc, const float* __restrict__ vw) {
    extern __shared__ char smem[];
    uint32_t sb = smem_u32(smem);
    int tid = threadIdx.x;
    int lane = tid & 31, wid = tid >> 5;
    int warpM = wid >> 2, warpN = wid & 3;
    int row_base = blockIdx.x * 128;
    int b = row_base >> 11;

    float* e_sm = (float*)smem;              // [128]
    float* wsb  = (float*)(smem + 512);      // [512]
    float* vv   = (float*)(smem + 2560);     // [512]
    if (tid < 128) e_sm[tid] = 0.f;
    for (int i = tid; i < N_ATT; i += 256) {
        wsb[i] = g_WsUb[(size_t)b * N_ATT + i];
        vv[i]  = vw[i];
    }
    __syncthreads();

    LoadCtx L{sb, enc, tid, row_base};

    // prologue: 2 tiles in flight
    load_tile(L, 0); load_tile(L, 1);

    // per-thread ldmatrix address components
    int arow0 = warpM * 64 + (lane & 7) + ((lane >> 3) & 1) * 8;  // + mb*16
    int ach   = (lane >> 4) & 1;
    int brow0 = warpN * 32 + (lane & 7) + ((lane >> 4) & 1) * 8;  // + p*16
    int bch   = (lane >> 3) & 1;
    int g = lane >> 2, t = lane & 3;

    #pragma unroll 1
    for (int pass = 0; pass < 4; pass++) {
        float acc[4][4][4];
        #pragma unroll
        for (int mb = 0; mb < 4; mb++)
            #pragma unroll
            for (int nb = 0; nb < 4; nb++)
                #pragma unroll
                for (int c = 0; c < 4; c++) acc[mb][nb][c] = 0.f;

        #pragma unroll 1
        for (int kt = 0; kt < 16; kt++) {
            int tc = pass * 16 + kt;
            if (tc < NTILES - 1) cp_wait<1>(); else cp_wait<0>();
            __syncthreads();
            if (tc + 2 < NTILES) load_tile(L, tc + 2);

            int s = tc % NSTAGE;
            uint32_t stA = sb + OFF_A16 + s * STG_A16;
            uint32_t stB = sb + OFF_B   + s * STG_B;

            if (pass == 0) {
                // convert A32[s] -> A16[s] (swizzled) + STG fp16 to g_encH
                uint32_t a32 = sb + OFF_A32 + s * STG_A32;
                #pragma unroll
                for (int i = 0; i < 4; i++) {
                    int o = tid + i * 256;
                    int r = o >> 3, cout = o & 7;
                    int sub = cout >> 2, cc = (cout & 3) * 2;
                    uint32_t base = a32 + sub * 16384 + r * 128;
                    float f0, f1, f2, f3, f4, f5, f6, f7;
                    uint32_t ad0 = base + (((uint32_t)(cc ^ (r & 7))) << 4);
                    uint32_t ad1 = base + (((uint32_t)((cc + 1) ^ (r & 7))) << 4);
                    asm volatile("ld.shared.v4.f32 {%0,%1,%2,%3}, [%4];"
                                 : "=f"(f0), "=f"(f1), "=f"(f2), "=f"(f3) : "r"(ad0));
                    asm volatile("ld.shared.v4.f32 {%0,%1,%2,%3}, [%4];"
                                 : "=f"(f4), "=f"(f5), "=f"(f6), "=f"(f7) : "r"(ad1));
                    __half2 h0 = __floats2half2_rn(f0, f1);
                    __half2 h1 = __floats2half2_rn(f2, f3);
                    __half2 h2 = __floats2half2_rn(f4, f5);
                    __half2 h3 = __floats2half2_rn(f6, f7);
                    uint32_t u0 = *reinterpret_cast<uint32_t*>(&h0);
                    uint32_t u1 = *reinterpret_cast<uint32_t*>(&h1);
                    uint32_t u2 = *reinterpret_cast<uint32_t*>(&h2);
                    uint32_t u3 = *reinterpret_cast<uint32_t*>(&h3);
                    uint32_t sts = stA + r * 128 + (((uint32_t)(cout ^ (r & 7))) << 4);
                    asm volatile("st.shared.v4.b32 [%0], {%1,%2,%3,%4};"
                                 :: "r"(sts), "r"(u0), "r"(u1), "r"(u2), "r"(u3)
                                 : "memory");
                    uint4* dst = reinterpret_cast<uint4*>(
                        g_encH + (size_t)(row_base + r) * N_ENC2 + kt * KT + cout * 8);
                    *dst = make_uint4(u0, u1, u2, u3);
                }
                __syncthreads();   // STS visible before ldmatrix
            }

            #pragma unroll
            for (int ks = 0; ks < 4; ks++) {       // each ks = K16
                uint32_t afr[4][4];
                #pragma unroll
                for (int mb = 0; mb < 4; mb++) {
                    int r = arow0 + mb * 16;
                    uint32_t addr = stA + r * 128 +
                        (((uint32_t)((2 * ks + ach) ^ (r & 7))) << 4);
                    ldsm4(addr, afr[mb][0], afr[mb][1], afr[mb][2], afr[mb][3]);
                }
                uint32_t bfr[4][2];
                #pragma unroll
                for (int p = 0; p < 2; p++) {
                    int r = brow0 + p * 16;
                    uint32_t addr = stB + r * 128 +
                        (((uint32_t)((2 * ks + bch) ^ (r & 7))) << 4);
                    uint32_t r0, r1, r2, r3;
                    ldsm4(addr, r0, r1, r2, r3);
                    bfr[2 * p][0] = r0; bfr[2 * p][1] = r1;
                    bfr[2 * p + 1][0] = r2; bfr[2 * p + 1][1] = r3;
                }
                #pragma unroll
                for (int mb = 0; mb < 4; mb++)
                    #pragma unroll
                    for (int nb = 0; nb < 4; nb++)
                        mma_f16(acc[mb][nb], afr[mb], bfr[nb]);
            }
        }

        // fused epilogue: energy += v . tanh(acc + wsb); overlaps in-flight cp.async
        #pragma unroll
        for (int mb = 0; mb < 4; mb++) {
            #pragma unroll
            for (int h = 0; h < 2; h++) {
                float rsum = 0.f;
                #pragma unroll
                for (int nb = 0; nb < 4; nb++) {
                    #pragma unroll
                    for (int c = 0; c < 2; c++) {
                        int col = pass * 128 + warpN * 32 + nb * 8 + 2 * t + c;
                        float x = acc[mb][nb][2 * h + c] + wsb[col];
                        rsum = fmaf(vv[col], tanh_acc(x), rsum);
                    }
                }
                rsum += __shfl_xor_sync(0xffffffffu, rsum, 1);
                rsum += __shfl_xor_sync(0xffffffffu, rsum, 2);
                if (t == 0)
                    atomicAdd(e_sm + warpM * 64 + mb * 16 + h * 8 + g, rsum);
            }
        }
    }
    __syncthreads();

    if (tid < 128) g_energy[row_base + tid] = e_sm[tid];
}

// ---------------- kernel 4: softmax over S=2048 per batch row ----------------
__global__ void softmax_kernel(float* __restrict__ out) {
    int b = blockIdx.x;
    int tid = threadIdx.x;
    const float* e = g_energy + (size_t)b * N_SEQ;
    float v[8];
    float mx = -1e30f;
    #pragma unroll
    for (int i = 0; i < 8; i++) { v[i] = e[tid + i * 256]; mx = fmaxf(mx, v[i]); }
    #pragma unroll
    for (int o = 16; o; o >>= 1) mx = fmaxf(mx, __shfl_xor_sync(0xFFFFFFFFu, mx, o));
    __shared__ float redm[8], reds[8];
    if ((tid & 31) == 0) redm[tid >> 5] = mx;
    __syncthreads();
    float m2 = redm[0];
    #pragma unroll
    for (int i = 1; i < 8; i++) m2 = fmaxf(m2, redm[i]);
    float sum = 0.f;
    #pragma unroll
    for (int i = 0; i < 8; i++) { v[i] = expf(v[i] - m2); sum += v[i]; }
    #pragma unroll
    for (int o = 16; o; o >>= 1) sum += __shfl_xor_sync(0xFFFFFFFFu, sum, o);
    if ((tid & 31) == 0) reds[tid >> 5] = sum;
    __syncthreads();
    float s2 = 0.f;
    #pragma unroll
    for (int i = 0; i < 8; i++) s2 += reds[i];
    float inv = 1.f / s2;
    #pragma unroll
    for (int i = 0; i < 8; i++) out[(size_t)b * N_SEQ + tid + i * 256] = v[i] * inv;
}

// ---------------- launch ----------------
extern "C" void kernel_launch(void* const* d_in, const int* in_sizes, int n_in,
                              void* d_out, int out_size) {
    const float* dec = (const float*)d_in[0];   // (32, 1024)
    const float* enc = (const float*)d_in[1];   // (32, 2048, 1024)
    const float* Ww  = (const float*)d_in[2];   // (1024, 512)
    const float* Wb  = (const float*)d_in[3];   // (512,)
    const float* Uw  = (const float*)d_in[4];   // (1024, 512)
    const float* Ub  = (const float*)d_in[5];   // (512,)
    const float* vw  = (const float*)d_in[6];   // (512, 1)
    float* out = (float*)d_out;                 // (32, 2048)

    cudaFuncSetAttribute(attn_energy_kernel,
                         cudaFuncAttributeMaxDynamicSharedMemorySize, SMEM_MAIN);

    ut_transpose_kernel<<<dim3(N_ATT / 32, N_ENC2 / 32), dim3(32, 8)>>>(Uw);
    wsb_kernel<<<dim3(2, 8), 256>>>(dec, Ww, Wb, Ub);
    attn_energy_kernel<<<N_ROWS / 128, 256, SMEM_MAIN>>>(enc, vw);
    softmax_kernel<<<N_BATCH, 256>>>(out);
}

// round 8
// speedup vs baseline: 1.0215x; 1.0215x over previous
#include <cuda_runtime.h>
#include <cuda_fp16.h>
#include <cstdint>

// ---------------- problem constants ----------------
#define N_ATT   512
#define N_DEC   1024
#define N_ENC2  1024
#define N_BATCH 32
#define N_SEQ   2048
#define N_ROWS  (N_BATCH * N_SEQ)   // 65536

// ---------------- device scratch ----------------
__device__ __half g_UTH[N_ATT * N_ENC2];            // U_w transposed fp16: [n][k]
__device__ float  g_WsUb[N_BATCH * N_ATT];          // dec@W_w + W_b + U_b
__device__ float  g_energy[N_ROWS];

// ---------------- helpers (plain sm_80+ PTX only) ----------------
__device__ __forceinline__ uint32_t smem_u32(const void* p) {
    uint32_t a;
    asm("{ .reg .u64 t; cvta.to.shared.u64 t, %1; cvt.u32.u64 %0, t; }"
        : "=r"(a) : "l"(p));
    return a;
}

__device__ __forceinline__ void cp16(uint32_t dst, const void* src) {
    asm volatile("cp.async.cg.shared.global [%0], [%1], 16;"
                 :: "r"(dst), "l"(src) : "memory");
}
__device__ __forceinline__ void cp_commit() {
    asm volatile("cp.async.commit_group;" ::: "memory");
}
template <int N>
__device__ __forceinline__ void cp_wait() {
    asm volatile("cp.async.wait_group %0;" :: "n"(N) : "memory");
}

__device__ __forceinline__ void ldsm4(uint32_t addr, uint32_t& r0, uint32_t& r1,
                                      uint32_t& r2, uint32_t& r3) {
    asm volatile("ldmatrix.sync.aligned.m8n8.x4.shared.b16 {%0,%1,%2,%3}, [%4];"
                 : "=r"(r0), "=r"(r1), "=r"(r2), "=r"(r3) : "r"(addr));
}

__device__ __forceinline__ void mma_f16(float* d, const uint32_t* a, const uint32_t* b) {
    asm volatile(
        "mma.sync.aligned.m16n8k16.row.col.f32.f16.f16.f32 "
        "{%0,%1,%2,%3}, {%4,%5,%6,%7}, {%8,%9}, {%0,%1,%2,%3};"
        : "+f"(d[0]), "+f"(d[1]), "+f"(d[2]), "+f"(d[3])
        : "r"(a[0]), "r"(a[1]), "r"(a[2]), "r"(a[3]), "r"(b[0]), "r"(b[1]));
}

// accurate tanh: 1 - 2/(exp(2x)+1) via ex2.approx + rcp.approx (~1e-6 err)
__device__ __forceinline__ float tanh_acc(float x) {
    float e, r;
    asm("ex2.approx.f32 %0, %1;" : "=f"(e) : "f"(x * 2.8853900817779268f));
    asm("rcp.approx.f32 %0, %1;" : "=f"(r) : "f"(e + 1.0f));
    return 1.0f - 2.0f * r;
}

// ---------------- kernel 1: transpose U_w into g_UTH[n][k] (fp16) ----------------
__global__ void ut_transpose_kernel(const float* __restrict__ Uw) {
    __shared__ float tile[32][33];
    int n0 = blockIdx.x * 32;
    int k0 = blockIdx.y * 32;
    int tx = threadIdx.x, ty = threadIdx.y;  // block (32, 8)
    #pragma unroll
    for (int j = 0; j < 32; j += 8)
        tile[ty + j][tx] = Uw[(size_t)(k0 + ty + j) * N_ATT + n0 + tx];
    __syncthreads();
    #pragma unroll
    for (int j = 0; j < 32; j += 8)
        g_UTH[(size_t)(n0 + ty + j) * N_ENC2 + k0 + tx] = __float2half_rn(tile[tx][ty + j]);
}

// ---------------- kernel 2: g_WsUb = dec @ W_w + W_b + U_b ----------------
__global__ void wsb_kernel(const float* __restrict__ dec, const float* __restrict__ Ww,
                           const float* __restrict__ Wb, const float* __restrict__ Ub) {
    int a = blockIdx.x * 256 + threadIdx.x;  // grid (2, 8)
    int b0 = blockIdx.y * 4;
    float acc[4] = {0.f, 0.f, 0.f, 0.f};
    #pragma unroll 2
    for (int k = 0; k < N_DEC; k++) {
        float w = Ww[(size_t)k * N_ATT + a];
        #pragma unroll
        for (int j = 0; j < 4; j++)
            acc[j] = fmaf(dec[(size_t)(b0 + j) * N_DEC + k], w, acc[j]);
    }
    float bias = Wb[a] + Ub[a];
    #pragma unroll
    for (int j = 0; j < 4; j++)
        g_WsUb[(size_t)(b0 + j) * N_ATT + a] = acc[j] + bias;
}

// ---------------- kernel 3: fp32-direct GEMM, convert-one-ahead pipeline ----------------
// 512 CTAs x 256 thr, 1 CTA/SM. CTA = 128 rows x 512 cols as TWO N=256 passes
// (acc 128 f32/thread, R2-proven geometry). A is read as fp32 each pass and
// converted to a double-buffered swizzled fp16 stage ONE TILE AHEAD of the MMA,
// so conversion overlaps MMA issue. B fp16 from g_UTH, 3 stages. One sync/tile.
// Flat tile counter tc = pass*16 + kt; NTILES = 32.
#define KT        64
#define STG_A16   16384                 // 128 rows * 128B fp16
#define STG_B     32768                 // 256 n-rows * 128B fp16
#define STG_A32   32768                 // 128 rows * 256B fp32 (two 32-col subtiles)
#define HDR       5120
#define OFF_A16   HDR                                // 2 buffers
#define OFF_B     (HDR + 2 * STG_A16)                // 3 buffers
#define OFF_A32   (OFF_B + 3 * STG_B)                // 2 buffers
#define SMEM_MAIN (OFF_A32 + 2 * STG_A32)            // 201728 B
#define NTILES    32

struct LoadCtx {
    uint32_t sb;
    const float* enc;
    int tid, row_base;
};

// load tile t: A32 (fp32, from enc) + B (fp16, from g_UTH); one commit group
__device__ __forceinline__ void load_tile(const LoadCtx& L, int t) {
    int kt = t & 15, pass = t >> 4;
    // A32: 128 rows x 64 fp32 = 2048 x 16B chunks, 2 subtiles of 32 cols
    uint32_t a32 = L.sb + OFF_A32 + (t & 1) * STG_A32;
    const float* Asrc = L.enc + (size_t)L.row_base * N_ENC2 + kt * KT;
    #pragma unroll
    for (int i = 0; i < 8; i++) {
        int q = L.tid + i * 256;
        int r = q >> 4, sub = (q >> 3) & 1, c = q & 7;
        cp16(a32 + sub * 16384 + r * 128 + (((uint32_t)(c ^ (r & 7))) << 4),
             Asrc + (size_t)r * N_ENC2 + sub * 32 + c * 4);
    }
    // B: 256 n-rows x 128B = 2048 x 16B chunks
    const __half* Bsrc = g_UTH + (size_t)(pass * 256) * N_ENC2 + kt * KT;
    uint32_t stB = L.sb + OFF_B + (t % 3) * STG_B;
    #pragma unroll
    for (int i = 0; i < 8; i++) {
        int id = L.tid + i * 256;
        int n = id >> 3, c = id & 7;
        cp16(stB + n * 128 + (((uint32_t)(c ^ (n & 7))) << 4),
             Bsrc + (size_t)n * N_ENC2 + c * 8);
    }
    cp_commit();
}

// convert A32[t&1] -> A16[t&1] (swizzled fp16, layout verified in R7)
__device__ __forceinline__ void convert_tile(uint32_t sb, int tid, int t) {
    uint32_t a32 = sb + OFF_A32 + (t & 1) * STG_A32;
    uint32_t a16 = sb + OFF_A16 + (t & 1) * STG_A16;
    #pragma unroll
    for (int i = 0; i < 4; i++) {
        int o = tid + i * 256;
        int r = o >> 3, cout = o & 7;
        int sub = cout >> 2, cc = (cout & 3) * 2;
        uint32_t base = a32 + sub * 16384 + r * 128;
        float f0, f1, f2, f3, f4, f5, f6, f7;
        uint32_t ad0 = base + (((uint32_t)(cc ^ (r & 7))) << 4);
        uint32_t ad1 = base + (((uint32_t)((cc + 1) ^ (r & 7))) << 4);
        asm volatile("ld.shared.v4.f32 {%0,%1,%2,%3}, [%4];"
                     : "=f"(f0), "=f"(f1), "=f"(f2), "=f"(f3) : "r"(ad0));
        asm volatile("ld.shared.v4.f32 {%0,%1,%2,%3}, [%4];"
                     : "=f"(f4), "=f"(f5), "=f"(f6), "=f"(f7) : "r"(ad1));
        __half2 h0 = __floats2half2_rn(f0, f1);
        __half2 h1 = __floats2half2_rn(f2, f3);
        __half2 h2 = __floats2half2_rn(f4, f5);
        __half2 h3 = __floats2half2_rn(f6, f7);
        uint32_t u0 = *reinterpret_cast<uint32_t*>(&h0);
        uint32_t u1 = *reinterpret_cast<uint32_t*>(&h1);
        uint32_t u2 = *reinterpret_cast<uint32_t*>(&h2);
        uint32_t u3 = *reinterpret_cast<uint32_t*>(&h3);
        uint32_t sts = a16 + r * 128 + (((uint32_t)(cout ^ (r & 7))) << 4);
        asm volatile("st.shared.v4.b32 [%0], {%1,%2,%3,%4};"
                     :: "r"(sts), "r"(u0), "r"(u1), "r"(u2), "r"(u3) : "memory");
    }
}

__global__ void __launch_bounds__(256, 1)
attn_energy_kernel(const float* __restrict__ enc, const float* __restrict__ vw) {
    extern __shared__ char smem[];
    uint32_t sb = smem_u32(smem);
    int tid = threadIdx.x;
    int lane = tid & 31, wid = tid >> 5;
    int warpM = wid >> 2, warpN = wid & 3;
    int row_base = blockIdx.x * 128;
    int b = row_base >> 11;

    float* e_sm = (float*)smem;              // [128]
    float* wsb  = (float*)(smem + 512);      // [512]
    float* vv   = (float*)(smem + 2560);     // [512]
    if (tid < 128) e_sm[tid] = 0.f;
    for (int i = tid; i < N_ATT; i += 256) {
        wsb[i] = g_WsUb[(size_t)b * N_ATT + i];
        vv[i]  = vw[i];
    }

    LoadCtx L{sb, enc, tid, row_base};

    // prologue: tiles 0 and 1 in flight; convert tile 0
    load_tile(L, 0);
    load_tile(L, 1);
    cp_wait<1>();          // tile 0 landed
    __syncthreads();
    convert_tile(sb, tid, 0);

    // per-thread ldmatrix address components (R2 geometry)
    int arow0 = warpM * 64 + (lane & 7) + ((lane >> 3) & 1) * 8;  // + mb*16
    int ach   = (lane >> 4) & 1;
    int brow0 = warpN * 64 + (lane & 7) + ((lane >> 4) & 1) * 8;  // + p*16
    int bch   = (lane >> 3) & 1;
    int g = lane >> 2, t = lane & 3;

    float acc[4][8][4];
    #pragma unroll
    for (int mb = 0; mb < 4; mb++)
        #pragma unroll
        for (int nb = 0; nb < 8; nb++)
            #pragma unroll
            for (int c = 0; c < 4; c++) acc[mb][nb][c] = 0.f;

    #pragma unroll 1
    for (int tc = 0; tc < NTILES; tc++) {
        cp_wait<0>();      // tile tc+1 landed (sole outstanding group)
        __syncthreads();   // all warps done with MMA(tc-1) + convert STS visible
        if (tc + 2 < NTILES) load_tile(L, tc + 2);
        if (tc + 1 < NTILES) convert_tile(sb, tid, tc + 1);  // overlaps MMA(tc)

        uint32_t stA = sb + OFF_A16 + (tc & 1) * STG_A16;
        uint32_t stB = sb + OFF_B + (tc % 3) * STG_B;
        #pragma unroll
        for (int ks = 0; ks < 4; ks++) {       // each ks = K16
            uint32_t afr[4][4];
            #pragma unroll
            for (int mb = 0; mb < 4; mb++) {
                int r = arow0 + mb * 16;
                uint32_t addr = stA + r * 128 +
                    (((uint32_t)((2 * ks + ach) ^ (r & 7))) << 4);
                ldsm4(addr, afr[mb][0], afr[mb][1], afr[mb][2], afr[mb][3]);
            }
            uint32_t bfr[8][2];
            #pragma unroll
            for (int p = 0; p < 4; p++) {
                int r = brow0 + p * 16;
                uint32_t addr = stB + r * 128 +
                    (((uint32_t)((2 * ks + bch) ^ (r & 7))) << 4);
                uint32_t r0, r1, r2, r3;
                ldsm4(addr, r0, r1, r2, r3);
                bfr[2 * p][0] = r0; bfr[2 * p][1] = r1;
                bfr[2 * p + 1][0] = r2; bfr[2 * p + 1][1] = r3;
            }
            #pragma unroll
            for (int mb = 0; mb < 4; mb++)
                #pragma unroll
                for (int nb = 0; nb < 8; nb++)
                    mma_f16(acc[mb][nb], afr[mb], bfr[nb]);
        }

        // end of a pass: drain accumulators through the fused energy epilogue
        if ((tc & 15) == 15) {
            int pass = tc >> 4;
            #pragma unroll
            for (int mb = 0; mb < 4; mb++) {
                #pragma unroll
                for (int h = 0; h < 2; h++) {
                    float rsum = 0.f;
                    #pragma unroll
                    for (int nb = 0; nb < 8; nb++) {
                        #pragma unroll
                        for (int c = 0; c < 2; c++) {
                            int col = pass * 256 + warpN * 64 + nb * 8 + 2 * t + c;
                            float x = acc[mb][nb][2 * h + c] + wsb[col];
                            rsum = fmaf(vv[col], tanh_acc(x), rsum);
                        }
                    }
                    rsum += __shfl_xor_sync(0xffffffffu, rsum, 1);
                    rsum += __shfl_xor_sync(0xffffffffu, rsum, 2);
                    if (t == 0)
                        atomicAdd(e_sm + warpM * 64 + mb * 16 + h * 8 + g, rsum);
                }
            }
            if (pass == 0) {
                #pragma unroll
                for (int mb = 0; mb < 4; mb++)
                    #pragma unroll
                    for (int nb = 0; nb < 8; nb++)
                        #pragma unroll
                        for (int c = 0; c < 4; c++) acc[mb][nb][c] = 0.f;
            }
        }
    }
    __syncthreads();

    if (tid < 128) g_energy[row_base + tid] = e_sm[tid];
}

// ---------------- kernel 4: softmax over S=2048 per batch row ----------------
__global__ void softmax_kernel(float* __restrict__ out) {
    int b = blockIdx.x;
    int tid = threadIdx.x;
    const float* e = g_energy + (size_t)b * N_SEQ;
    float v[8];
    float mx = -1e30f;
    #pragma unroll
    for (int i = 0; i < 8; i++) { v[i] = e[tid + i * 256]; mx = fmaxf(mx, v[i]); }
    #pragma unroll
    for (int o = 16; o; o >>= 1) mx = fmaxf(mx, __shfl_xor_sync(0xFFFFFFFFu, mx, o));
    __shared__ float redm[8], reds[8];
    if ((tid & 31) == 0) redm[tid >> 5] = mx;
    __syncthreads();
    float m2 = redm[0];
    #pragma unroll
    for (int i = 1; i < 8; i++) m2 = fmaxf(m2, redm[i]);
    float sum = 0.f;
    #pragma unroll
    for (int i = 0; i < 8; i++) { v[i] = expf(v[i] - m2); sum += v[i]; }
    #pragma unroll
    for (int o = 16; o; o >>= 1) sum += __shfl_xor_sync(0xFFFFFFFFu, sum, o);
    if ((tid & 31) == 0) reds[tid >> 5] = sum;
    __syncthreads();
    float s2 = 0.f;
    #pragma unroll
    for (int i = 0; i < 8; i++) s2 += reds[i];
    float inv = 1.f / s2;
    #pragma unroll
    for (int i = 0; i < 8; i++) out[(size_t)b * N_SEQ + tid + i * 256] = v[i] * inv;
}

// ---------------- launch ----------------
extern "C" void kernel_launch(void* const* d_in, const int* in_sizes, int n_in,
                              void* d_out, int out_size) {
    const float* dec = (const float*)d_in[0];   // (32, 1024)
    const float* enc = (const float*)d_in[1];   // (32, 2048, 1024)
    const float* Ww  = (const float*)d_in[2];   // (1024, 512)
    const float* Wb  = (const float*)d_in[3];   // (512,)
    const float* Uw  = (const float*)d_in[4];   // (1024, 512)
    const float* Ub  = (const float*)d_in[5];   // (512,)
    const float* vw  = (const float*)d_in[6];   // (512, 1)
    float* out = (float*)d_out;                 // (32, 2048)

    cudaFuncSetAttribute(attn_energy_kernel,
                         cudaFuncAttributeMaxDynamicSharedMemorySize, SMEM_MAIN);

    ut_transpose_kernel<<<dim3(N_ATT / 32, N_ENC2 / 32), dim3(32, 8)>>>(Uw);
    wsb_kernel<<<dim3(2, 8), 256>>>(dec, Ww, Wb, Ub);
    attn_energy_kernel<<<N_ROWS / 128, 256, SMEM_MAIN>>>(enc, vw);
    softmax_kernel<<<N_BATCH, 256>>>(out);
}

// round 9
// speedup vs baseline: 1.4770x; 1.4460x over previous
#include <cuda_runtime.h>
#include <cuda_fp16.h>
#include <cstdint>

// ---------------- problem constants ----------------
#define N_ATT   512
#define N_DEC   1024
#define N_ENC2  1024
#define N_BATCH 32
#define N_SEQ   2048
#define N_ROWS  (N_BATCH * N_SEQ)   // 65536

// ---------------- device scratch (static globals; no runtime allocation) ----------------
__device__ __half g_encH[(size_t)N_ROWS * N_ENC2];  // fp16 copy of encoder (128 MB)
__device__ __half g_UTH[N_ATT * N_ENC2];            // U_w transposed fp16: [n][k]
__device__ float  g_WsUb[N_BATCH * N_ATT];          // dec@W_w + W_b + U_b
__device__ float  g_energy[N_ROWS];

// ---------------- helpers (plain sm_80+ PTX only) ----------------
__device__ __forceinline__ uint32_t smem_u32(const void* p) {
    uint32_t a;
    asm("{ .reg .u64 t; cvta.to.shared.u64 t, %1; cvt.u32.u64 %0, t; }"
        : "=r"(a) : "l"(p));
    return a;
}

__device__ __forceinline__ void cp16(uint32_t dst, const void* src) {
    asm volatile("cp.async.cg.shared.global [%0], [%1], 16;"
                 :: "r"(dst), "l"(src) : "memory");
}
__device__ __forceinline__ void cp_commit() {
    asm volatile("cp.async.commit_group;" ::: "memory");
}
template <int N>
__device__ __forceinline__ void cp_wait() {
    asm volatile("cp.async.wait_group %0;" :: "n"(N) : "memory");
}

__device__ __forceinline__ void ldsm4(uint32_t addr, uint32_t& r0, uint32_t& r1,
                                      uint32_t& r2, uint32_t& r3) {
    asm volatile("ldmatrix.sync.aligned.m8n8.x4.shared.b16 {%0,%1,%2,%3}, [%4];"
                 : "=r"(r0), "=r"(r1), "=r"(r2), "=r"(r3) : "r"(addr));
}

__device__ __forceinline__ void mma_f16(float* d, const uint32_t* a, const uint32_t* b) {
    asm volatile(
        "mma.sync.aligned.m16n8k16.row.col.f32.f16.f16.f32 "
        "{%0,%1,%2,%3}, {%4,%5,%6,%7}, {%8,%9}, {%0,%1,%2,%3};"
        : "+f"(d[0]), "+f"(d[1]), "+f"(d[2]), "+f"(d[3])
        : "r"(a[0]), "r"(a[1]), "r"(a[2]), "r"(a[3]), "r"(b[0]), "r"(b[1]));
}

// accurate tanh: 1 - 2/(exp(2x)+1) via ex2.approx + rcp.approx (~1e-6 err)
__device__ __forceinline__ float tanh_acc(float x) {
    float e, r;
    asm("ex2.approx.f32 %0, %1;" : "=f"(e) : "f"(x * 2.8853900817779268f));
    asm("rcp.approx.f32 %0, %1;" : "=f"(r) : "f"(e + 1.0f));
    return 1.0f - 2.0f * r;
}

// ---------------- kernel 0: fp32 -> fp16 encoder conversion ----------------
// Block-strided, fully coalesced: each thread does 4 independent 16B loads
// (MLP=4, hoisted) and 4 coalesced 8B stores. 16384 blocks x 256 threads.
__global__ void conv_kernel(const float4* __restrict__ src) {
    size_t base = (size_t)blockIdx.x * 1024 + threadIdx.x;
    float4 v0 = src[base];
    float4 v1 = src[base + 256];
    float4 v2 = src[base + 512];
    float4 v3 = src[base + 768];
    uint2* dst = reinterpret_cast<uint2*>(g_encH);
    __half2 a0 = __floats2half2_rn(v0.x, v0.y), a1 = __floats2half2_rn(v0.z, v0.w);
    __half2 b0 = __floats2half2_rn(v1.x, v1.y), b1 = __floats2half2_rn(v1.z, v1.w);
    __half2 c0 = __floats2half2_rn(v2.x, v2.y), c1 = __floats2half2_rn(v2.z, v2.w);
    __half2 d0 = __floats2half2_rn(v3.x, v3.y), d1 = __floats2half2_rn(v3.z, v3.w);
    dst[base]       = make_uint2(*(uint32_t*)&a0, *(uint32_t*)&a1);
    dst[base + 256] = make_uint2(*(uint32_t*)&b0, *(uint32_t*)&b1);
    dst[base + 512] = make_uint2(*(uint32_t*)&c0, *(uint32_t*)&c1);
    dst[base + 768] = make_uint2(*(uint32_t*)&d0, *(uint32_t*)&d1);
}

// ---------------- kernel 1: transpose U_w into g_UTH[n][k] (fp16) ----------------
__global__ void ut_transpose_kernel(const float* __restrict__ Uw) {
    __shared__ float tile[32][33];
    int n0 = blockIdx.x * 32;
    int k0 = blockIdx.y * 32;
    int tx = threadIdx.x, ty = threadIdx.y;  // block (32, 8)
    #pragma unroll
    for (int j = 0; j < 32; j += 8)
        tile[ty + j][tx] = Uw[(size_t)(k0 + ty + j) * N_ATT + n0 + tx];
    __syncthreads();
    #pragma unroll
    for (int j = 0; j < 32; j += 8)
        g_UTH[(size_t)(n0 + ty + j) * N_ENC2 + k0 + tx] = __float2half_rn(tile[tx][ty + j]);
}

// ---------------- kernel 2: g_WsUb = dec @ W_w + W_b + U_b ----------------
__global__ void wsb_kernel(const float* __restrict__ dec, const float* __restrict__ Ww,
                           const float* __restrict__ Wb, const float* __restrict__ Ub) {
    int a = blockIdx.x * 256 + threadIdx.x;  // grid (2, 32)
    int b = blockIdx.y;
    const float* dr = dec + (size_t)b * N_DEC;
    float a0 = 0.f, a1 = 0.f, a2 = 0.f, a3 = 0.f;
    #pragma unroll 4
    for (int k = 0; k < N_DEC; k += 4) {
        a0 = fmaf(dr[k + 0], Ww[(size_t)(k + 0) * N_ATT + a], a0);
        a1 = fmaf(dr[k + 1], Ww[(size_t)(k + 1) * N_ATT + a], a1);
        a2 = fmaf(dr[k + 2], Ww[(size_t)(k + 2) * N_ATT + a], a2);
        a3 = fmaf(dr[k + 3], Ww[(size_t)(k + 3) * N_ATT + a], a3);
    }
    g_WsUb[(size_t)b * N_ATT + a] = (a0 + a1) + (a2 + a3) + Wb[a] + Ub[a];
}

// ---------------- kernel 3: fp16 mma.sync GEMM + fused energy epilogue ----------------
// (R4-proven: 234us, at the legacy-HMMA floor.)
// 512 CTAs x 256 thr, 2 CTAs/SM (regs capped at 128 via launch_bounds).
// CTA = 128 rows x 512 cols done as FOUR N=128 passes (acc 64 f32/thread).
// K-tile 64 fp16 (128B rows, XOR-swizzled), 3-stage cp.async pipeline,
// flat tile counter tc = pass*16 + kt. Warp layout: 2(M) x 4(N), warp tile 64x32.
#define KT        64
#define NSTAGE    3
#define STG_A     16384                 // 128 rows * 128B
#define STG_B     16384                 // 128 n-rows * 128B
#define STG_BYTES (STG_A + STG_B)
#define HDR       5120                  // e_sm(512) + wsb(2048) + vv(2048) + pad
#define SMEM_MAIN (HDR + NSTAGE * STG_BYTES)   // 103424 B -> 2 CTAs/SM
#define NTILES    64                    // 4 passes * 16 K-tiles

struct LoadCtx {
    uint32_t sb;
    int tid, row_base;
};

__device__ __forceinline__ void load_tile(const LoadCtx& L, int tc) {
    int pass = tc >> 4, kt = tc & 15;
    uint32_t st = L.sb + HDR + (tc % NSTAGE) * STG_BYTES;
    const __half* Asrc = g_encH + (size_t)L.row_base * N_ENC2 + kt * KT;
    #pragma unroll
    for (int i = 0; i < 4; i++) {
        int id = L.tid + i * 256;
        int r = id >> 3, c = id & 7;
        cp16(st + r * 128 + (((uint32_t)(c ^ (r & 7))) << 4),
             Asrc + (size_t)r * N_ENC2 + c * 8);
    }
    const __half* Bsrc = g_UTH + (size_t)(pass * 128) * N_ENC2 + kt * KT;
    uint32_t stB = st + STG_A;
    #pragma unroll
    for (int i = 0; i < 4; i++) {
        int id = L.tid + i * 256;
        int n = id >> 3, c = id & 7;
        cp16(stB + n * 128 + (((uint32_t)(c ^ (n & 7))) << 4),
             Bsrc + (size_t)n * N_ENC2 + c * 8);
    }
    cp_commit();
}

__global__ void __launch_bounds__(256, 2)
attn_energy_kernel(const float* __restrict__ vw) {
    extern __shared__ char smem[];
    uint32_t sb = smem_u32(smem);
    int tid = threadIdx.x;
    int lane = tid & 31, wid = tid >> 5;
    int warpM = wid >> 2, warpN = wid & 3;
    int row_base = blockIdx.x * 128;
    int b = row_base >> 11;

    float* e_sm = (float*)smem;              // [128]
    float* wsb  = (float*)(smem + 512);      // [512]
    float* vv   = (float*)(smem + 2560);     // [512]
    if (tid < 128) e_sm[tid] = 0.f;
    for (int i = tid; i < N_ATT; i += 256) {
        wsb[i] = g_WsUb[(size_t)b * N_ATT + i];
        vv[i]  = vw[i];
    }

    LoadCtx L{sb, tid, row_base};

    // prologue: 2 tiles in flight
    load_tile(L, 0); load_tile(L, 1);

    // per-thread ldmatrix address components
    int arow0 = warpM * 64 + (lane & 7) + ((lane >> 3) & 1) * 8;  // + mb*16
    int ach   = (lane >> 4) & 1;
    int brow0 = warpN * 32 + (lane & 7) + ((lane >> 4) & 1) * 8;  // + p*16
    int bch   = (lane >> 3) & 1;
    int g = lane >> 2, t = lane & 3;

    #pragma unroll 1
    for (int pass = 0; pass < 4; pass++) {
        float acc[4][4][4];
        #pragma unroll
        for (int mb = 0; mb < 4; mb++)
            #pragma unroll
            for (int nb = 0; nb < 4; nb++)
                #pragma unroll
                for (int c = 0; c < 4; c++) acc[mb][nb][c] = 0.f;

        #pragma unroll 1
        for (int kt = 0; kt < 16; kt++) {
            int tc = pass * 16 + kt;
            if (tc < NTILES - 1) cp_wait<1>(); else cp_wait<0>();
            __syncthreads();
            if (tc + 2 < NTILES) load_tile(L, tc + 2);

            uint32_t st  = sb + HDR + (tc % NSTAGE) * STG_BYTES;
            uint32_t stB = st + STG_A;
            #pragma unroll
            for (int ks = 0; ks < 4; ks++) {       // each ks = K16
                uint32_t afr[4][4];
                #pragma unroll
                for (int mb = 0; mb < 4; mb++) {
                    int r = arow0 + mb * 16;
                    uint32_t addr = st + r * 128 +
                        (((uint32_t)((2 * ks + ach) ^ (r & 7))) << 4);
                    ldsm4(addr, afr[mb][0], afr[mb][1], afr[mb][2], afr[mb][3]);
                }
                uint32_t bfr[4][2];
                #pragma unroll
                for (int p = 0; p < 2; p++) {
                    int r = brow0 + p * 16;
                    uint32_t addr = stB + r * 128 +
                        (((uint32_t)((2 * ks + bch) ^ (r & 7))) << 4);
                    uint32_t r0, r1, r2, r3;
                    ldsm4(addr, r0, r1, r2, r3);
                    bfr[2 * p][0] = r0; bfr[2 * p][1] = r1;
                    bfr[2 * p + 1][0] = r2; bfr[2 * p + 1][1] = r3;
                }
                #pragma unroll
                for (int mb = 0; mb < 4; mb++)
                    #pragma unroll
                    for (int nb = 0; nb < 4; nb++)
                        mma_f16(acc[mb][nb], afr[mb], bfr[nb]);
            }
        }

        // fused epilogue: energy += v . tanh(acc + wsb); overlaps in-flight cp.async
        #pragma unroll
        for (int mb = 0; mb < 4; mb++) {
            #pragma unroll
            for (int h = 0; h < 2; h++) {
                float rsum = 0.f;
                #pragma unroll
                for (int nb = 0; nb < 4; nb++) {
                    #pragma unroll
                    for (int c = 0; c < 2; c++) {
                        int col = pass * 128 + warpN * 32 + nb * 8 + 2 * t + c;
                        float x = acc[mb][nb][2 * h + c] + wsb[col];
                        rsum = fmaf(vv[col], tanh_acc(x), rsum);
                    }
                }
                rsum += __shfl_xor_sync(0xffffffffu, rsum, 1);
                rsum += __shfl_xor_sync(0xffffffffu, rsum, 2);
                if (t == 0)
                    atomicAdd(e_sm + warpM * 64 + mb * 16 + h * 8 + g, rsum);
            }
        }
    }
    __syncthreads();

    if (tid < 128) g_energy[row_base + tid] = e_sm[tid];
}

// ---------------- kernel 4: softmax over S=2048 per batch row ----------------
__global__ void softmax_kernel(float* __restrict__ out) {
    int b = blockIdx.x;
    int tid = threadIdx.x;
    const float* e = g_energy + (size_t)b * N_SEQ;
    float v[8];
    float mx = -1e30f;
    #pragma unroll
    for (int i = 0; i < 8; i++) { v[i] = e[tid + i * 256]; mx = fmaxf(mx, v[i]); }
    #pragma unroll
    for (int o = 16; o; o >>= 1) mx = fmaxf(mx, __shfl_xor_sync(0xFFFFFFFFu, mx, o));
    __shared__ float redm[8], reds[8];
    if ((tid & 31) == 0) redm[tid >> 5] = mx;
    __syncthreads();
    float m2 = redm[0];
    #pragma unroll
    for (int i = 1; i < 8; i++) m2 = fmaxf(m2, redm[i]);
    float sum = 0.f;
    #pragma unroll
    for (int i = 0; i < 8; i++) { v[i] = expf(v[i] - m2); sum += v[i]; }
    #pragma unroll
    for (int o = 16; o; o >>= 1) sum += __shfl_xor_sync(0xFFFFFFFFu, sum, o);
    if ((tid & 31) == 0) reds[tid >> 5] = sum;
    __syncthreads();
    float s2 = 0.f;
    #pragma unroll
    for (int i = 0; i < 8; i++) s2 += reds[i];
    float inv = 1.f / s2;
    #pragma unroll
    for (int i = 0; i < 8; i++) out[(size_t)b * N_SEQ + tid + i * 256] = v[i] * inv;
}

// ---------------- launch ----------------
extern "C" void kernel_launch(void* const* d_in, const int* in_sizes, int n_in,
                              void* d_out, int out_size) {
    const float* dec = (const float*)d_in[0];   // (32, 1024)
    const float* enc = (const float*)d_in[1];   // (32, 2048, 1024)
    const float* Ww  = (const float*)d_in[2];   // (1024, 512)
    const float* Wb  = (const float*)d_in[3];   // (512,)
    const float* Uw  = (const float*)d_in[4];   // (1024, 512)
    const float* Ub  = (const float*)d_in[5];   // (512,)
    const float* vw  = (const float*)d_in[6];   // (512, 1)
    float* out = (float*)d_out;                 // (32, 2048)

    cudaFuncSetAttribute(attn_energy_kernel,
                         cudaFuncAttributeMaxDynamicSharedMemorySize, SMEM_MAIN);

    conv_kernel<<<(N_ROWS * (N_ENC2 / 4)) / 1024, 256>>>((const float4*)enc);
    ut_transpose_kernel<<<dim3(N_ATT / 32, N_ENC2 / 32), dim3(32, 8)>>>(Uw);
    wsb_kernel<<<dim3(2, N_BATCH), 256>>>(dec, Ww, Wb, Ub);
    attn_energy_kernel<<<N_ROWS / 128, 256, SMEM_MAIN>>>(vw);
    softmax_kernel<<<N_BATCH, 256>>>(out);
}